// round 1
// baseline (speedup 1.0000x reference)
#include <cuda_runtime.h>
#include <cuda_bf16.h>

// GraphAggregation: out[b, :] = mean over 196 nodes of in[b].reshape(196, 4)
// Input : (B, 784) fp32, row = 196 contiguous float4 "node" vectors (3136 B, 16B aligned)
// Output: (B, 4) fp32
//
// One warp per row. Lane l loads float4 nodes l, l+32, ... (<=7 loads),
// coalesced 512B per warp-instruction. Warp shfl-xor reduce of the 4-vector,
// lane 0 writes the float4 mean. Pure HBM-bound: ~411 MB read @ ~8 TB/s.

#define N_NODES 196
#define DINV (1.0f / 196.0f)

__global__ __launch_bounds__(256, 8)
void graph_agg_kernel(const float4* __restrict__ in, float4* __restrict__ out, int B)
{
    const int warp_in_block = threadIdx.x >> 5;
    const int lane = threadIdx.x & 31;
    const int row = blockIdx.x * (blockDim.x >> 5) + warp_in_block;
    if (row >= B) return;

    const float4* row_ptr = in + (size_t)row * N_NODES;

    float sx = 0.f, sy = 0.f, sz = 0.f, sw = 0.f;

    // 196 = 6*32 + 4 : lanes 0..3 do 7 loads, others 6.
    #pragma unroll
    for (int k = 0; k < 7; ++k) {
        int idx = k * 32 + lane;
        if (idx < N_NODES) {
            float4 v = __ldg(row_ptr + idx);
            sx += v.x; sy += v.y; sz += v.z; sw += v.w;
        }
    }

    // Warp tree reduction of the 4-vector.
    #pragma unroll
    for (int off = 16; off > 0; off >>= 1) {
        sx += __shfl_xor_sync(0xFFFFFFFFu, sx, off);
        sy += __shfl_xor_sync(0xFFFFFFFFu, sy, off);
        sz += __shfl_xor_sync(0xFFFFFFFFu, sz, off);
        sw += __shfl_xor_sync(0xFFFFFFFFu, sw, off);
    }

    if (lane == 0) {
        float4 r;
        r.x = sx * DINV;
        r.y = sy * DINV;
        r.z = sz * DINV;
        r.w = sw * DINV;
        out[row] = r;
    }
}

extern "C" void kernel_launch(void* const* d_in, const int* in_sizes, int n_in,
                              void* d_out, int out_size)
{
    const float4* in = (const float4*)d_in[0];
    float4* out = (float4*)d_out;
    const int B = in_sizes[0] / (N_NODES * 4);   // 131072

    const int warps_per_block = 8;               // 256 threads
    const int blocks = (B + warps_per_block - 1) / warps_per_block;
    graph_agg_kernel<<<blocks, warps_per_block * 32>>>(in, out, B);
}

// round 2
// speedup vs baseline: 1.0010x; 1.0010x over previous
#include <cuda_runtime.h>
#include <cuda_bf16.h>

// GraphAggregation: out[b, :] = mean over 196 nodes of in[b].reshape(196, 4)
// Input : (B, 784) fp32 == (B, 196) float4, rows contiguous (3136 B each)
// Output: (B, 4) fp32 == (B) float4
//
// One warp per row, fully coalesced 512B warp-transactions.
// R1 fix: drop the __launch_bounds__ min-blocks clamp (regs=31 was
// serializing the loads). Front-batch 6 unconditional float4 LDGs into
// distinct registers + 1 predicated tail -> MLP ~7 per thread, enough to
// hide DRAM latency at ~48 warps/SM and pin the HBM roofline.

#define N_NODES 196
#define DINV (1.0f / 196.0f)

__global__ __launch_bounds__(256)
void graph_agg_kernel(const float4* __restrict__ in, float4* __restrict__ out, int B)
{
    const int warp_in_block = threadIdx.x >> 5;
    const int lane = threadIdx.x & 31;
    const int row = blockIdx.x * (blockDim.x >> 5) + warp_in_block;
    if (row >= B) return;

    const float4* __restrict__ row_ptr = in + (size_t)row * N_NODES + lane;

    // Front-batched independent loads (6 full strides of 32 nodes).
    float4 v0 = __ldg(row_ptr +   0);
    float4 v1 = __ldg(row_ptr +  32);
    float4 v2 = __ldg(row_ptr +  64);
    float4 v3 = __ldg(row_ptr +  96);
    float4 v4 = __ldg(row_ptr + 128);
    float4 v5 = __ldg(row_ptr + 160);
    // Tail: nodes 192..195 -> lanes 0..3 only (predicated load).
    float4 v6 = make_float4(0.f, 0.f, 0.f, 0.f);
    if (lane < 4) v6 = __ldg(row_ptr + 192);

    // Pairwise sum tree (keeps dependency chains short).
    float sx = ((v0.x + v1.x) + (v2.x + v3.x)) + ((v4.x + v5.x) + v6.x);
    float sy = ((v0.y + v1.y) + (v2.y + v3.y)) + ((v4.y + v5.y) + v6.y);
    float sz = ((v0.z + v1.z) + (v2.z + v3.z)) + ((v4.z + v5.z) + v6.z);
    float sw = ((v0.w + v1.w) + (v2.w + v3.w)) + ((v4.w + v5.w) + v6.w);

    // Warp tree reduction of the 4-vector.
    #pragma unroll
    for (int off = 16; off > 0; off >>= 1) {
        sx += __shfl_xor_sync(0xFFFFFFFFu, sx, off);
        sy += __shfl_xor_sync(0xFFFFFFFFu, sy, off);
        sz += __shfl_xor_sync(0xFFFFFFFFu, sz, off);
        sw += __shfl_xor_sync(0xFFFFFFFFu, sw, off);
    }

    if (lane == 0) {
        float4 r;
        r.x = sx * DINV;
        r.y = sy * DINV;
        r.z = sz * DINV;
        r.w = sw * DINV;
        out[row] = r;
    }
}

extern "C" void kernel_launch(void* const* d_in, const int* in_sizes, int n_in,
                              void* d_out, int out_size)
{
    const float4* in = (const float4*)d_in[0];
    float4* out = (float4*)d_out;
    const int B = in_sizes[0] / (N_NODES * 4);   // 131072

    const int warps_per_block = 8;               // 256 threads
    const int blocks = (B + warps_per_block - 1) / warps_per_block;
    graph_agg_kernel<<<blocks, warps_per_block * 32>>>(in, out, B);
}